// round 15
// baseline (speedup 1.0000x reference)
#include <cuda_runtime.h>
#include <cuda_fp16.h>
#include <math.h>
#include <stdint.h>

// ---------------------------------------------------------------------------
// Problem constants
// ---------------------------------------------------------------------------
#define B_    2
#define N_    8192
#define C_    2048
#define H_    16
#define HD_   128
#define GS_   256
#define G_    (N_/GS_)     // 32
#define HALF_ 8
#define SHIFT_ 128
#define SCALE_ 0.08838834764831843f   // 1/sqrt(128)
#define NEGF  -1e9f

#define MROWS (B_*N_)      // 16384

// scratch
__device__ __half g_A[(size_t)MROWS * C_];               // x fp16 [16384][2048]
__device__ __half g_B[(size_t)3 * C_ * C_];              // W fp16 [3][2048][2048]
__device__ __half g_q[(size_t)3 * B_ * H_ * N_ * HD_];   // qkv fp16 (shifted)

// ---------------------------------------------------------------------------
// fused convert: fp32 -> fp16 for x, Wq, Wk, Wv in ONE launch (proven R14, 44us)
// ---------------------------------------------------------------------------
#define XBLK 32768
#define WBLK 4096

__global__ __launch_bounds__(256) void conv_kernel(
    const float* __restrict__ x,
    const float* __restrict__ Wq, const float* __restrict__ Wk,
    const float* __restrict__ Wv,
    __half* __restrict__ Ag, __half* __restrict__ Bg)
{
    const float* in;
    __half* out;
    size_t base;
    int bid = blockIdx.x;
    if (bid < XBLK) {
        in = x; out = Ag; base = (size_t)bid * 256;
    } else {
        int wsel = (bid - XBLK) / WBLK;
        in  = (wsel == 0) ? Wq : (wsel == 1) ? Wk : Wv;
        out = Bg + (size_t)wsel * C_ * C_;
        base = (size_t)((bid - XBLK) % WBLK) * 256;
    }
    size_t idx = base + threadIdx.x;
    float4 v = ((const float4*)in)[idx];
    __half2* o = (__half2*)(out + idx * 4);
    o[0] = __floats2half2_rn(v.x, v.y);
    o[1] = __floats2half2_rn(v.z, v.w);
}

// ---------------------------------------------------------------------------
// common MMA helpers (fragment idioms proven R5-R14)
// ---------------------------------------------------------------------------
__device__ __forceinline__ uint32_t s2u(const void* p) {
    uint32_t a;
    asm("{ .reg .u64 t; cvta.to.shared.u64 t, %1; cvt.u32.u64 %0, t; }"
        : "=r"(a) : "l"(p));
    return a;
}
__device__ __forceinline__ void ldmx4(uint32_t* r, uint32_t addr) {
    asm volatile("ldmatrix.sync.aligned.m8n8.x4.shared.b16 {%0,%1,%2,%3}, [%4];"
                 : "=r"(r[0]), "=r"(r[1]), "=r"(r[2]), "=r"(r[3]) : "r"(addr));
}
__device__ __forceinline__ void ldmx4t(uint32_t* r, uint32_t addr) {
    asm volatile("ldmatrix.sync.aligned.m8n8.x4.trans.shared.b16 {%0,%1,%2,%3}, [%4];"
                 : "=r"(r[0]), "=r"(r[1]), "=r"(r[2]), "=r"(r[3]) : "r"(addr));
}
__device__ __forceinline__ void mma16816(float* c, const uint32_t* a,
                                         uint32_t b0, uint32_t b1) {
    asm volatile(
        "mma.sync.aligned.m16n8k16.row.col.f32.f16.f16.f32 "
        "{%0,%1,%2,%3}, {%4,%5,%6,%7}, {%8,%9}, {%0,%1,%2,%3};"
        : "+f"(c[0]), "+f"(c[1]), "+f"(c[2]), "+f"(c[3])
        : "r"(a[0]), "r"(a[1]), "r"(a[2]), "r"(a[3]), "r"(b0), "r"(b1));
}
__device__ __forceinline__ void cp16(uint32_t dst, const void* src) {
    asm volatile("cp.async.cg.shared.global [%0], [%1], 16;"
                 :: "r"(dst), "l"(src) : "memory");
}

// ---------------------------------------------------------------------------
// HMMA GEMM v5: CTA 128x128, 4 warps, warp tile 64x64 (LDSM:MMA ratio 4.0),
// KC=64, 3-stage cp.async, 2 CTAs/SM (256 thr/SM -> 256-reg cap).
// ---------------------------------------------------------------------------
#define KC      64
#define NCHG    (C_/KC)        // 32
#define GROWB   144            // 64 fp16 (128 B) + 16 pad
#define GSTAGE  (256*GROWB)    // 36864 B
#define GM_SMEM (3*GSTAGE)     // 110592 B -> 2 CTAs/SM

__global__ __launch_bounds__(128, 2) void gemm_kernel(
    const float* __restrict__ bq, const float* __restrict__ bk,
    const float* __restrict__ bv)
{
    extern __shared__ char smg[];
    const uint32_t smb = s2u(smg);

    const int tid  = threadIdx.x;
    const int wid  = tid >> 5, lane = tid & 31;
    const int wm   = wid & 1;          // 2 warp rows x 64
    const int wn   = wid >> 1;         // 2 warp cols x 64
    const int lrow = lane & 15;
    const int lcol = (lane >> 4) * 8;

    const int n0 = blockIdx.x * 128;
    const int m0 = blockIdx.y * 128;
    const int z  = blockIdx.z;
    const __half* __restrict__ Ap = g_A + (size_t)m0 * C_;
    const __half* __restrict__ Bp = g_B + (size_t)z * C_ * C_ + (size_t)n0 * C_;
    const float* __restrict__ bias = (z == 0) ? bq : (z == 1) ? bk : bv;

    float acc[4][8][4];
    #pragma unroll
    for (int i = 0; i < 4; i++)
        #pragma unroll
        for (int j = 0; j < 8; j++)
            #pragma unroll
            for (int k = 0; k < 4; k++) acc[i][j][k] = 0.f;

    auto fetch = [&](int c) {
        const int s = c - (c / 3) * 3;
        const size_t k0 = (size_t)c * KC;
        const uint32_t base = smb + s * GSTAGE;
        #pragma unroll
        for (int i = 0; i < 8; i++) {            // A: 128 rows x 128 B
            int f = tid + 128 * i, row = f >> 3, cc = (f & 7) * 16;
            cp16(base + row * GROWB + cc, Ap + (size_t)row * C_ + k0 + cc / 2);
        }
        #pragma unroll
        for (int i = 0; i < 8; i++) {            // B: 128 rows x 128 B
            int f = tid + 128 * i, row = f >> 3, cc = (f & 7) * 16;
            cp16(base + 128 * GROWB + row * GROWB + cc,
                 Bp + (size_t)row * C_ + k0 + cc / 2);
        }
        asm volatile("cp.async.commit_group;" ::: "memory");
    };

    fetch(0); fetch(1);

    for (int c = 0; c < NCHG; c++) {
        if (c + 1 < NCHG) asm volatile("cp.async.wait_group 1;" ::: "memory");
        else              asm volatile("cp.async.wait_group 0;" ::: "memory");
        __syncthreads();
        if (c + 2 < NCHG) fetch(c + 2);

        const int s = c - (c / 3) * 3;
        const uint32_t aB = smb + s * GSTAGE;
        const uint32_t bB = aB + 128 * GROWB;
        #pragma unroll
        for (int ks = 0; ks < 4; ks++) {
            const int kb = 2 * (ks * 16 + lcol);
            uint32_t afr[4][4];
            #pragma unroll
            for (int mi = 0; mi < 4; mi++)
                ldmx4(afr[mi], aB + (wm * 64 + mi * 16 + lrow) * GROWB + kb);
            #pragma unroll
            for (int nb = 0; nb < 4; nb++) {
                uint32_t bm[4];
                ldmx4(bm, bB + (wn * 64 + nb * 16 + lrow) * GROWB + kb);
                #pragma unroll
                for (int mi = 0; mi < 4; mi++) {
                    mma16816(acc[mi][2 * nb],     afr[mi], bm[0], bm[2]);
                    mma16816(acc[mi][2 * nb + 1], afr[mi], bm[1], bm[3]);
                }
            }
        }
    }

    // epilogue: fragments -> g_q (bias + shift), fp16
    const size_t PSZ = (size_t)B_ * H_ * N_ * HD_;
    __half* qp = g_q + (size_t)z * PSZ;
    const int qrow = lane >> 2;
    const int qcol = (lane & 3) * 2;

    #pragma unroll
    for (int mi = 0; mi < 4; mi++) {
        #pragma unroll
        for (int hf = 0; hf < 2; hf++) {
            const int m  = m0 + wm * 64 + mi * 16 + qrow + hf * 8;
            const int b  = m >> 13;
            const int ns = m & (N_ - 1);
            #pragma unroll
            for (int ni = 0; ni < 8; ni++) {
                const int n = n0 + wn * 64 + ni * 8 + qcol;
                const int hh = n >> 7;
                const int d  = n & (HD_ - 1);
                const int nd = (hh < HALF_) ? ns : ((ns - SHIFT_) & (N_ - 1));
                const size_t off = (((size_t)b * H_ + hh) * N_ + nd) * HD_ + d;
                float v0 = acc[mi][ni][hf * 2 + 0] + bias[n];
                float v1 = acc[mi][ni][hf * 2 + 1] + bias[n + 1];
                *(__half2*)(qp + off) = __floats2half2_rn(v0, v1);
            }
        }
    }
}

// ---------------------------------------------------------------------------
// FA2 fp16 attention (exact R13, proven): CTA = (qt, g, b*h), 128 thr, 4 warps,
// 4 CTAs/SM. Single-pass QK and PV. 32-row K/V chunks, double-buffered.
// ---------------------------------------------------------------------------
#define AQ_STR  272
#define KCH_B   (32*AQ_STR)         // 8704 per chunk buffer
#define OFF_AK  (64*AQ_STR)         // 17408 (after Q)
#define OFF_AV  (OFF_AK + 2*KCH_B)  // 34816
#define AT_SMEM (OFF_AV + 2*KCH_B)  // 52224 -> 4 CTAs/SM

__global__ __launch_bounds__(128, 4) void attn_kernel(float* __restrict__ y)
{
    extern __shared__ char smc[];
    const uint32_t smb = s2u(smc);
    const int tid  = threadIdx.x;
    const int w    = tid >> 5, lane = tid & 31;
    const int lrow = lane & 15, lcol = (lane >> 4) * 8;

    const int qt = blockIdx.x;               // 0..3
    const int g  = blockIdx.y;               // 0..31
    const int bh = blockIdx.z;
    const int b  = bh >> 4;
    const int h  = bh & 15;

    const size_t TOT   = (size_t)B_ * H_ * N_ * HD_;
    const size_t plane = ((size_t)b * H_ + h) * (size_t)N_ * HD_;
    const __half* qp = g_q + plane + (size_t)(g * GS_ + qt * 64) * HD_;
    const __half* kp = g_q + TOT     + plane + (size_t)(g * GS_) * HD_;
    const __half* vp = g_q + 2 * TOT + plane + (size_t)(g * GS_) * HD_;

    // load Q tile: 64 rows x 256 B
    #pragma unroll
    for (int i = 0; i < 8; i++) {
        int f = tid + 128 * i, r = f >> 4, c8 = (f & 15) * 8;
        *(uint4*)(smc + r * AQ_STR + 2 * c8) =
            *(const uint4*)(qp + (size_t)r * HD_ + c8);
    }

    // async fetch of 32-row K/V chunk c into buffer c&1
    auto fetchkv = [&](int c) {
        const int bsel = c & 1;
        const uint32_t kb = smb + OFF_AK + bsel * KCH_B;
        const uint32_t vb = smb + OFF_AV + bsel * KCH_B;
        #pragma unroll
        for (int i = 0; i < 4; i++) {
            int f = tid + 128 * i;
            int r = f >> 4;
            int u = f & 15;
            const size_t row = (size_t)(c * 32 + r) * HD_;
            cp16(kb + r * AQ_STR + u * 16, kp + row + u * 8);
        }
        #pragma unroll
        for (int i = 0; i < 4; i++) {
            int f = tid + 128 * i;
            int r = f >> 4;
            int u = f & 15;
            const size_t row = (size_t)(c * 32 + r) * HD_;
            cp16(vb + r * AQ_STR + u * 16, vp + row + u * 8);
        }
        asm volatile("cp.async.commit_group;" ::: "memory");
    };

    float m0 = -1e30f, m1 = -1e30f, l0 = 0.f, l1 = 0.f;
    float accO[16][4];
    #pragma unroll
    for (int i = 0; i < 16; i++)
        #pragma unroll
        for (int j = 0; j < 4; j++) accO[i][j] = 0.f;

    const int NCHK = 2 * (qt + 1);
    fetchkv(0);

    for (int c = 0; c < NCHK; c++) {
        if (c + 1 < NCHK) {
            fetchkv(c + 1);
            asm volatile("cp.async.wait_group 1;" ::: "memory");
        } else {
            asm volatile("cp.async.wait_group 0;" ::: "memory");
        }
        __syncthreads();   // chunk c visible (also Q stores on first iter)

        const uint32_t kbuf = smb + OFF_AK + (c & 1) * KCH_B;
        const uint32_t vbuf = smb + OFF_AV + (c & 1) * KCH_B;

        // ---- S = Q . K^T for 32 K-rows (single fp16 pass, k=128) ----
        float s[4][4];
        #pragma unroll
        for (int i = 0; i < 4; i++)
            #pragma unroll
            for (int j = 0; j < 4; j++) s[i][j] = 0.f;

        #pragma unroll
        for (int ks = 0; ks < 8; ks++) {
            uint32_t afr[4];
            ldmx4(afr, smb + (w * 16 + lrow) * AQ_STR + 2 * (ks * 16 + lcol));
            #pragma unroll
            for (int nb = 0; nb < 2; nb++) {
                uint32_t bm[4];
                ldmx4(bm, kbuf + (nb * 16 + lrow) * AQ_STR + 2 * (ks * 16 + lcol));
                mma16816(s[nb * 2],     afr, bm[0], bm[2]);
                mma16816(s[nb * 2 + 1], afr, bm[1], bm[3]);
            }
        }

        // ---- scale + causal mask (only tail chunks can mask) ----
        #pragma unroll
        for (int nt = 0; nt < 4; nt++)
            #pragma unroll
            for (int j = 0; j < 4; j++) s[nt][j] *= SCALE_;
        if (c >= 2 * qt) {
            const int r0 = qt * 64 + w * 16 + (lane >> 2);
            const int r1 = r0 + 8;
            #pragma unroll
            for (int nt = 0; nt < 4; nt++) {
                const int col = c * 32 + nt * 8 + (lane & 3) * 2;
                if (col     > r0) s[nt][0] = NEGF;
                if (col + 1 > r0) s[nt][1] = NEGF;
                if (col     > r1) s[nt][2] = NEGF;
                if (col + 1 > r1) s[nt][3] = NEGF;
            }
        }

        // ---- online softmax (rows r0, r1) ----
        float tm0 = -1e30f, tm1 = -1e30f;
        #pragma unroll
        for (int nt = 0; nt < 4; nt++) {
            tm0 = fmaxf(tm0, fmaxf(s[nt][0], s[nt][1]));
            tm1 = fmaxf(tm1, fmaxf(s[nt][2], s[nt][3]));
        }
        tm0 = fmaxf(tm0, __shfl_xor_sync(~0u, tm0, 1));
        tm0 = fmaxf(tm0, __shfl_xor_sync(~0u, tm0, 2));
        tm1 = fmaxf(tm1, __shfl_xor_sync(~0u, tm1, 1));
        tm1 = fmaxf(tm1, __shfl_xor_sync(~0u, tm1, 2));

        const float mn0 = fmaxf(m0, tm0), mn1 = fmaxf(m1, tm1);
        const float a0 = __expf(m0 - mn0), a1 = __expf(m1 - mn1);
        float rs0 = 0.f, rs1 = 0.f;
        #pragma unroll
        for (int nt = 0; nt < 4; nt++) {
            s[nt][0] = __expf(s[nt][0] - mn0); rs0 += s[nt][0];
            s[nt][1] = __expf(s[nt][1] - mn0); rs0 += s[nt][1];
            s[nt][2] = __expf(s[nt][2] - mn1); rs1 += s[nt][2];
            s[nt][3] = __expf(s[nt][3] - mn1); rs1 += s[nt][3];
        }
        rs0 += __shfl_xor_sync(~0u, rs0, 1); rs0 += __shfl_xor_sync(~0u, rs0, 2);
        rs1 += __shfl_xor_sync(~0u, rs1, 1); rs1 += __shfl_xor_sync(~0u, rs1, 2);
        l0 = l0 * a0 + rs0;  l1 = l1 * a1 + rs1;
        m0 = mn0;            m1 = mn1;
        #pragma unroll
        for (int dt = 0; dt < 16; dt++) {
            accO[dt][0] *= a0; accO[dt][1] *= a0;
            accO[dt][2] *= a1; accO[dt][3] *= a1;
        }

        // ---- P (C-frag -> A-frag, fp16) . V (32 rows, single pass) ----
        #pragma unroll
        for (int kk = 0; kk < 2; kk++) {
            uint32_t ph[4];
            auto mkh = [&](float p0, float p1) -> uint32_t {
                __half2 hp = __floats2half2_rn(p0, p1);
                return *(uint32_t*)&hp;
            };
            ph[0] = mkh(s[2 * kk][0],     s[2 * kk][1]);
            ph[1] = mkh(s[2 * kk][2],     s[2 * kk][3]);
            ph[2] = mkh(s[2 * kk + 1][0], s[2 * kk + 1][1]);
            ph[3] = mkh(s[2 * kk + 1][2], s[2 * kk + 1][3]);
            #pragma unroll
            for (int dt = 0; dt < 8; dt++) {
                uint32_t bm[4];
                ldmx4t(bm, vbuf + (kk * 16 + lrow) * AQ_STR
                            + 2 * (dt * 16 + lcol));
                mma16816(accO[dt * 2],     ph, bm[0], bm[1]);
                mma16816(accO[dt * 2 + 1], ph, bm[2], bm[3]);
            }
        }
        __syncthreads();   // all reads of buffer c&1 done before it is refilled
    }

    // ---- epilogue: normalize, unshift + head-interleave into y ----
    const float i0 = 1.f / l0, i1 = 1.f / l1;
    const int row = w * 16 + (lane >> 2);
    const int np0 = g * GS_ + qt * 64 + row;
    const int np1 = np0 + 8;
    const int nf0 = (h < HALF_) ? np0 : ((np0 + SHIFT_) & (N_ - 1));
    const int nf1 = (h < HALF_) ? np1 : ((np1 + SHIFT_) & (N_ - 1));
    float* y0 = y + ((size_t)b * N_ + nf0) * C_ + h * HD_;
    float* y1 = y + ((size_t)b * N_ + nf1) * C_ + h * HD_;
    #pragma unroll
    for (int dt = 0; dt < 16; dt++) {
        const int d = dt * 8 + (lane & 3) * 2;
        *(float2*)(y0 + d) = make_float2(accO[dt][0] * i0, accO[dt][1] * i0);
        *(float2*)(y1 + d) = make_float2(accO[dt][2] * i1, accO[dt][3] * i1);
    }
}

// ---------------------------------------------------------------------------
extern "C" void kernel_launch(void* const* d_in, const int* in_sizes, int n_in,
                              void* d_out, int out_size)
{
    const float* x  = (const float*)d_in[0];
    const float* Wq = (const float*)d_in[1];
    const float* bq = (const float*)d_in[2];
    const float* Wk = (const float*)d_in[3];
    const float* bk = (const float*)d_in[4];
    const float* Wv = (const float*)d_in[5];
    const float* bv = (const float*)d_in[6];
    float* y = (float*)d_out;

    __half *Ag, *Bg;
    cudaGetSymbolAddress((void**)&Ag, g_A);
    cudaGetSymbolAddress((void**)&Bg, g_B);

    // fused fp32->fp16 converts (one launch)
    conv_kernel<<<XBLK + 3 * WBLK, 256>>>(x, Wq, Wk, Wv, Ag, Bg);

    // fp16 HMMA projections v5 (64x64 warp tile, 128 thr, 2 CTAs/SM)
    cudaFuncSetAttribute(gemm_kernel,
                         cudaFuncAttributeMaxDynamicSharedMemorySize, GM_SMEM);
    gemm_kernel<<<dim3(C_ / 128, MROWS / 128, 3), 128, GM_SMEM>>>(bq, bk, bv);

    // fp16 FA2 attention (proven R13)
    cudaFuncSetAttribute(attn_kernel,
                         cudaFuncAttributeMaxDynamicSharedMemorySize, AT_SMEM);
    attn_kernel<<<dim3(4, G_, B_ * H_), 128, AT_SMEM>>>(y);
}

// round 16
// speedup vs baseline: 1.0572x; 1.0572x over previous
#include <cuda_runtime.h>
#include <cuda_fp16.h>
#include <math.h>
#include <stdint.h>

// ---------------------------------------------------------------------------
// Problem constants
// ---------------------------------------------------------------------------
#define B_    2
#define N_    8192
#define C_    2048
#define H_    16
#define HD_   128
#define GS_   256
#define G_    (N_/GS_)     // 32
#define HALF_ 8
#define SHIFT_ 128
#define SCALE_ 0.08838834764831843f   // 1/sqrt(128)
#define NEGF  -1e9f

#define MROWS (B_*N_)      // 16384

// scratch
__device__ __half g_A[(size_t)MROWS * C_];               // x fp16 [16384][2048]
__device__ __half g_B[(size_t)3 * C_ * C_];              // W fp16 [3][2048][2048]
__device__ __half g_q[(size_t)3 * B_ * H_ * N_ * HD_];   // qkv fp16 (shifted)

// ---------------------------------------------------------------------------
// fused convert: fp32 -> fp16 for x, Wq, Wk, Wv in ONE launch (proven R14)
// ---------------------------------------------------------------------------
#define XBLK 32768
#define WBLK 4096

__global__ __launch_bounds__(256) void conv_kernel(
    const float* __restrict__ x,
    const float* __restrict__ Wq, const float* __restrict__ Wk,
    const float* __restrict__ Wv,
    __half* __restrict__ Ag, __half* __restrict__ Bg)
{
    const float* in;
    __half* out;
    size_t base;
    int bid = blockIdx.x;
    if (bid < XBLK) {
        in = x; out = Ag; base = (size_t)bid * 256;
    } else {
        int wsel = (bid - XBLK) / WBLK;
        in  = (wsel == 0) ? Wq : (wsel == 1) ? Wk : Wv;
        out = Bg + (size_t)wsel * C_ * C_;
        base = (size_t)((bid - XBLK) % WBLK) * 256;
    }
    size_t idx = base + threadIdx.x;
    float4 v = ((const float4*)in)[idx];
    __half2* o = (__half2*)(out + idx * 4);
    o[0] = __floats2half2_rn(v.x, v.y);
    o[1] = __floats2half2_rn(v.z, v.w);
}

// ---------------------------------------------------------------------------
// common MMA helpers (fragment idioms proven R5-R15)
// ---------------------------------------------------------------------------
__device__ __forceinline__ uint32_t s2u(const void* p) {
    uint32_t a;
    asm("{ .reg .u64 t; cvta.to.shared.u64 t, %1; cvt.u32.u64 %0, t; }"
        : "=r"(a) : "l"(p));
    return a;
}
__device__ __forceinline__ void ldmx4(uint32_t* r, uint32_t addr) {
    asm volatile("ldmatrix.sync.aligned.m8n8.x4.shared.b16 {%0,%1,%2,%3}, [%4];"
                 : "=r"(r[0]), "=r"(r[1]), "=r"(r[2]), "=r"(r[3]) : "r"(addr));
}
__device__ __forceinline__ void ldmx4t(uint32_t* r, uint32_t addr) {
    asm volatile("ldmatrix.sync.aligned.m8n8.x4.trans.shared.b16 {%0,%1,%2,%3}, [%4];"
                 : "=r"(r[0]), "=r"(r[1]), "=r"(r[2]), "=r"(r[3]) : "r"(addr));
}
__device__ __forceinline__ void mma16816(float* c, const uint32_t* a,
                                         uint32_t b0, uint32_t b1) {
    asm volatile(
        "mma.sync.aligned.m16n8k16.row.col.f32.f16.f16.f32 "
        "{%0,%1,%2,%3}, {%4,%5,%6,%7}, {%8,%9}, {%0,%1,%2,%3};"
        : "+f"(c[0]), "+f"(c[1]), "+f"(c[2]), "+f"(c[3])
        : "r"(a[0]), "r"(a[1]), "r"(a[2]), "r"(a[3]), "r"(b0), "r"(b1));
}
__device__ __forceinline__ void cp16(uint32_t dst, const void* src) {
    asm volatile("cp.async.cg.shared.global [%0], [%1], 16;"
                 :: "r"(dst), "l"(src) : "memory");
}

// ---------------------------------------------------------------------------
// HMMA GEMM (exact R13, proven 950us): K=2048 single pass, tile 128x128,
// warp 32x64, KC=64, 3-stage cp.async, 256 thr, 2 CTAs/SM.
// ---------------------------------------------------------------------------
#define KC      64
#define NCHG    (C_/KC)        // 32
#define GROWB   144            // 64 fp16 (128 B) + 16 pad
#define GSTAGE  (256*GROWB)    // 36864 B
#define GM_SMEM (3*GSTAGE)     // 110592 B -> 2 CTAs/SM

__global__ __launch_bounds__(256, 2) void gemm_kernel(
    const float* __restrict__ bq, const float* __restrict__ bk,
    const float* __restrict__ bv)
{
    extern __shared__ char smg[];
    const uint32_t smb = s2u(smg);

    const int tid  = threadIdx.x;
    const int wid  = tid >> 5, lane = tid & 31;
    const int wm   = wid & 3;
    const int wn   = wid >> 2;
    const int lrow = lane & 15;
    const int lcol = (lane >> 4) * 8;

    const int n0 = blockIdx.x * 128;
    const int m0 = blockIdx.y * 128;
    const int z  = blockIdx.z;
    const __half* __restrict__ Ap = g_A + (size_t)m0 * C_;
    const __half* __restrict__ Bp = g_B + (size_t)z * C_ * C_ + (size_t)n0 * C_;
    const float* __restrict__ bias = (z == 0) ? bq : (z == 1) ? bk : bv;

    float acc[2][8][4];
    #pragma unroll
    for (int i = 0; i < 2; i++)
        #pragma unroll
        for (int j = 0; j < 8; j++)
            #pragma unroll
            for (int k = 0; k < 4; k++) acc[i][j][k] = 0.f;

    auto fetch = [&](int c) {
        const int s = c - (c / 3) * 3;
        const size_t k0 = (size_t)c * KC;
        const uint32_t base = smb + s * GSTAGE;
        #pragma unroll
        for (int i = 0; i < 4; i++) {
            int f = tid + 256 * i, row = f >> 3, cc = (f & 7) * 16;
            cp16(base + row * GROWB + cc, Ap + (size_t)row * C_ + k0 + cc / 2);
        }
        #pragma unroll
        for (int i = 0; i < 4; i++) {
            int f = tid + 256 * i, row = f >> 3, cc = (f & 7) * 16;
            cp16(base + 128 * GROWB + row * GROWB + cc,
                 Bp + (size_t)row * C_ + k0 + cc / 2);
        }
        asm volatile("cp.async.commit_group;" ::: "memory");
    };

    fetch(0); fetch(1);

    for (int c = 0; c < NCHG; c++) {
        if (c + 1 < NCHG) asm volatile("cp.async.wait_group 1;" ::: "memory");
        else              asm volatile("cp.async.wait_group 0;" ::: "memory");
        __syncthreads();
        if (c + 2 < NCHG) fetch(c + 2);

        const int s = c - (c / 3) * 3;
        const uint32_t aB = smb + s * GSTAGE;
        const uint32_t bB = aB + 128 * GROWB;
        #pragma unroll
        for (int ks = 0; ks < 4; ks++) {
            const int kb = 2 * (ks * 16 + lcol);
            uint32_t afr[2][4];
            #pragma unroll
            for (int mi = 0; mi < 2; mi++)
                ldmx4(afr[mi], aB + (wm * 32 + mi * 16 + lrow) * GROWB + kb);
            #pragma unroll
            for (int nb = 0; nb < 4; nb++) {
                uint32_t bm[4];
                ldmx4(bm, bB + (wn * 64 + nb * 16 + lrow) * GROWB + kb);
                #pragma unroll
                for (int mi = 0; mi < 2; mi++) {
                    mma16816(acc[mi][2 * nb],     afr[mi], bm[0], bm[2]);
                    mma16816(acc[mi][2 * nb + 1], afr[mi], bm[1], bm[3]);
                }
            }
        }
    }

    // epilogue: fragments -> g_q (bias + shift), fp16
    const size_t PSZ = (size_t)B_ * H_ * N_ * HD_;
    __half* qp = g_q + (size_t)z * PSZ;
    const int qrow = lane >> 2;
    const int qcol = (lane & 3) * 2;

    #pragma unroll
    for (int mi = 0; mi < 2; mi++) {
        #pragma unroll
        for (int hf = 0; hf < 2; hf++) {
            const int m  = m0 + wm * 32 + mi * 16 + qrow + hf * 8;
            const int b  = m >> 13;
            const int ns = m & (N_ - 1);
            #pragma unroll
            for (int ni = 0; ni < 8; ni++) {
                const int n = n0 + wn * 64 + ni * 8 + qcol;
                const int hh = n >> 7;
                const int d  = n & (HD_ - 1);
                const int nd = (hh < HALF_) ? ns : ((ns - SHIFT_) & (N_ - 1));
                const size_t off = (((size_t)b * H_ + hh) * N_ + nd) * HD_ + d;
                float v0 = acc[mi][ni][hf * 2 + 0] + bias[n];
                float v1 = acc[mi][ni][hf * 2 + 1] + bias[n + 1];
                *(__half2*)(qp + off) = __floats2half2_rn(v0, v1);
            }
        }
    }
}

// ---------------------------------------------------------------------------
// FA2 fp16 attention (R13 + masked-chunk skip): CTA = (qt, g, b*h), 128 thr,
// 4 warps, 4 CTAs/SM. 32-row K/V chunks, double-buffered cp.async.
// Warp w skips chunk c entirely when c*32 > qt*64 + w*16 + 15 (all-masked).
// ---------------------------------------------------------------------------
#define AQ_STR  272
#define KCH_B   (32*AQ_STR)         // 8704 per chunk buffer
#define OFF_AK  (64*AQ_STR)         // 17408 (after Q)
#define OFF_AV  (OFF_AK + 2*KCH_B)  // 34816
#define AT_SMEM (OFF_AV + 2*KCH_B)  // 52224 -> 4 CTAs/SM

__global__ __launch_bounds__(128, 4) void attn_kernel(float* __restrict__ y)
{
    extern __shared__ char smc[];
    const uint32_t smb = s2u(smc);
    const int tid  = threadIdx.x;
    const int w    = tid >> 5, lane = tid & 31;
    const int lrow = lane & 15, lcol = (lane >> 4) * 8;

    const int qt = blockIdx.x;               // 0..3
    const int g  = blockIdx.y;               // 0..31
    const int bh = blockIdx.z;
    const int b  = bh >> 4;
    const int h  = bh & 15;

    const size_t TOT   = (size_t)B_ * H_ * N_ * HD_;
    const size_t plane = ((size_t)b * H_ + h) * (size_t)N_ * HD_;
    const __half* qp = g_q + plane + (size_t)(g * GS_ + qt * 64) * HD_;
    const __half* kp = g_q + TOT     + plane + (size_t)(g * GS_) * HD_;
    const __half* vp = g_q + 2 * TOT + plane + (size_t)(g * GS_) * HD_;

    // load Q tile: 64 rows x 256 B
    #pragma unroll
    for (int i = 0; i < 8; i++) {
        int f = tid + 128 * i, r = f >> 4, c8 = (f & 15) * 8;
        *(uint4*)(smc + r * AQ_STR + 2 * c8) =
            *(const uint4*)(qp + (size_t)r * HD_ + c8);
    }

    // async fetch of 32-row K/V chunk c into buffer c&1
    auto fetchkv = [&](int c) {
        const int bsel = c & 1;
        const uint32_t kb = smb + OFF_AK + bsel * KCH_B;
        const uint32_t vb = smb + OFF_AV + bsel * KCH_B;
        #pragma unroll
        for (int i = 0; i < 4; i++) {
            int f = tid + 128 * i;
            int r = f >> 4;
            int u = f & 15;
            const size_t row = (size_t)(c * 32 + r) * HD_;
            cp16(kb + r * AQ_STR + u * 16, kp + row + u * 8);
        }
        #pragma unroll
        for (int i = 0; i < 4; i++) {
            int f = tid + 128 * i;
            int r = f >> 4;
            int u = f & 15;
            const size_t row = (size_t)(c * 32 + r) * HD_;
            cp16(vb + r * AQ_STR + u * 16, vp + row + u * 8);
        }
        asm volatile("cp.async.commit_group;" ::: "memory");
    };

    float m0 = -1e30f, m1 = -1e30f, l0 = 0.f, l1 = 0.f;
    float accO[16][4];
    #pragma unroll
    for (int i = 0; i < 16; i++)
        #pragma unroll
        for (int j = 0; j < 4; j++) accO[i][j] = 0.f;

    const int NCHK = 2 * (qt + 1);
    fetchkv(0);

    for (int c = 0; c < NCHK; c++) {
        if (c + 1 < NCHK) {
            fetchkv(c + 1);
            asm volatile("cp.async.wait_group 1;" ::: "memory");
        } else {
            asm volatile("cp.async.wait_group 0;" ::: "memory");
        }
        __syncthreads();   // chunk c visible (also Q stores on first iter)

        // fully-masked chunk for this warp's rows? (warp-uniform guard)
        if (c * 32 <= qt * 64 + w * 16 + 15) {

        const uint32_t kbuf = smb + OFF_AK + (c & 1) * KCH_B;
        const uint32_t vbuf = smb + OFF_AV + (c & 1) * KCH_B;

        // ---- S = Q . K^T for 32 K-rows (single fp16 pass, k=128) ----
        float s[4][4];
        #pragma unroll
        for (int i = 0; i < 4; i++)
            #pragma unroll
            for (int j = 0; j < 4; j++) s[i][j] = 0.f;

        #pragma unroll
        for (int ks = 0; ks < 8; ks++) {
            uint32_t afr[4];
            ldmx4(afr, smb + (w * 16 + lrow) * AQ_STR + 2 * (ks * 16 + lcol));
            #pragma unroll
            for (int nb = 0; nb < 2; nb++) {
                uint32_t bm[4];
                ldmx4(bm, kbuf + (nb * 16 + lrow) * AQ_STR + 2 * (ks * 16 + lcol));
                mma16816(s[nb * 2],     afr, bm[0], bm[2]);
                mma16816(s[nb * 2 + 1], afr, bm[1], bm[3]);
            }
        }

        // ---- scale + causal mask (only tail chunks can mask) ----
        #pragma unroll
        for (int nt = 0; nt < 4; nt++)
            #pragma unroll
            for (int j = 0; j < 4; j++) s[nt][j] *= SCALE_;
        if (c >= 2 * qt) {
            const int r0 = qt * 64 + w * 16 + (lane >> 2);
            const int r1 = r0 + 8;
            #pragma unroll
            for (int nt = 0; nt < 4; nt++) {
                const int col = c * 32 + nt * 8 + (lane & 3) * 2;
                if (col     > r0) s[nt][0] = NEGF;
                if (col + 1 > r0) s[nt][1] = NEGF;
                if (col     > r1) s[nt][2] = NEGF;
                if (col + 1 > r1) s[nt][3] = NEGF;
            }
        }

        // ---- online softmax (rows r0, r1) ----
        float tm0 = -1e30f, tm1 = -1e30f;
        #pragma unroll
        for (int nt = 0; nt < 4; nt++) {
            tm0 = fmaxf(tm0, fmaxf(s[nt][0], s[nt][1]));
            tm1 = fmaxf(tm1, fmaxf(s[nt][2], s[nt][3]));
        }
        tm0 = fmaxf(tm0, __shfl_xor_sync(~0u, tm0, 1));
        tm0 = fmaxf(tm0, __shfl_xor_sync(~0u, tm0, 2));
        tm1 = fmaxf(tm1, __shfl_xor_sync(~0u, tm1, 1));
        tm1 = fmaxf(tm1, __shfl_xor_sync(~0u, tm1, 2));

        const float mn0 = fmaxf(m0, tm0), mn1 = fmaxf(m1, tm1);
        const float a0 = __expf(m0 - mn0), a1 = __expf(m1 - mn1);
        float rs0 = 0.f, rs1 = 0.f;
        #pragma unroll
        for (int nt = 0; nt < 4; nt++) {
            s[nt][0] = __expf(s[nt][0] - mn0); rs0 += s[nt][0];
            s[nt][1] = __expf(s[nt][1] - mn0); rs0 += s[nt][1];
            s[nt][2] = __expf(s[nt][2] - mn1); rs1 += s[nt][2];
            s[nt][3] = __expf(s[nt][3] - mn1); rs1 += s[nt][3];
        }
        rs0 += __shfl_xor_sync(~0u, rs0, 1); rs0 += __shfl_xor_sync(~0u, rs0, 2);
        rs1 += __shfl_xor_sync(~0u, rs1, 1); rs1 += __shfl_xor_sync(~0u, rs1, 2);
        l0 = l0 * a0 + rs0;  l1 = l1 * a1 + rs1;
        m0 = mn0;            m1 = mn1;
        #pragma unroll
        for (int dt = 0; dt < 16; dt++) {
            accO[dt][0] *= a0; accO[dt][1] *= a0;
            accO[dt][2] *= a1; accO[dt][3] *= a1;
        }

        // ---- P (C-frag -> A-frag, fp16) . V (32 rows, single pass) ----
        #pragma unroll
        for (int kk = 0; kk < 2; kk++) {
            uint32_t ph[4];
            auto mkh = [&](float p0, float p1) -> uint32_t {
                __half2 hp = __floats2half2_rn(p0, p1);
                return *(uint32_t*)&hp;
            };
            ph[0] = mkh(s[2 * kk][0],     s[2 * kk][1]);
            ph[1] = mkh(s[2 * kk][2],     s[2 * kk][3]);
            ph[2] = mkh(s[2 * kk + 1][0], s[2 * kk + 1][1]);
            ph[3] = mkh(s[2 * kk + 1][2], s[2 * kk + 1][3]);
            #pragma unroll
            for (int dt = 0; dt < 8; dt++) {
                uint32_t bm[4];
                ldmx4t(bm, vbuf + (kk * 16 + lrow) * AQ_STR
                            + 2 * (dt * 16 + lcol));
                mma16816(accO[dt * 2],     ph, bm[0], bm[1]);
                mma16816(accO[dt * 2 + 1], ph, bm[2], bm[3]);
            }
        }

        }  // end fully-masked skip guard

        __syncthreads();   // all reads of buffer c&1 done before it is refilled
    }

    // ---- epilogue: normalize, unshift + head-interleave into y ----
    const float i0 = 1.f / l0, i1 = 1.f / l1;
    const int row = w * 16 + (lane >> 2);
    const int np0 = g * GS_ + qt * 64 + row;
    const int np1 = np0 + 8;
    const int nf0 = (h < HALF_) ? np0 : ((np0 + SHIFT_) & (N_ - 1));
    const int nf1 = (h < HALF_) ? np1 : ((np1 + SHIFT_) & (N_ - 1));
    float* y0 = y + ((size_t)b * N_ + nf0) * C_ + h * HD_;
    float* y1 = y + ((size_t)b * N_ + nf1) * C_ + h * HD_;
    #pragma unroll
    for (int dt = 0; dt < 16; dt++) {
        const int d = dt * 8 + (lane & 3) * 2;
        *(float2*)(y0 + d) = make_float2(accO[dt][0] * i0, accO[dt][1] * i0);
        *(float2*)(y1 + d) = make_float2(accO[dt][2] * i1, accO[dt][3] * i1);
    }
}

// ---------------------------------------------------------------------------
extern "C" void kernel_launch(void* const* d_in, const int* in_sizes, int n_in,
                              void* d_out, int out_size)
{
    const float* x  = (const float*)d_in[0];
    const float* Wq = (const float*)d_in[1];
    const float* bq = (const float*)d_in[2];
    const float* Wk = (const float*)d_in[3];
    const float* bk = (const float*)d_in[4];
    const float* Wv = (const float*)d_in[5];
    const float* bv = (const float*)d_in[6];
    float* y = (float*)d_out;

    __half *Ag, *Bg;
    cudaGetSymbolAddress((void**)&Ag, g_A);
    cudaGetSymbolAddress((void**)&Bg, g_B);

    // fused fp32->fp16 converts (one launch, 5.7 TB/s)
    conv_kernel<<<XBLK + 3 * WBLK, 256>>>(x, Wq, Wk, Wv, Ag, Bg);

    // fp16 HMMA projections (exact R13 config)
    cudaFuncSetAttribute(gemm_kernel,
                         cudaFuncAttributeMaxDynamicSharedMemorySize, GM_SMEM);
    gemm_kernel<<<dim3(C_ / 128, MROWS / 128, 3), 256, GM_SMEM>>>(bq, bk, bv);

    // fp16 FA2 attention (R13 + masked-chunk skip)
    cudaFuncSetAttribute(attn_kernel,
                         cudaFuncAttributeMaxDynamicSharedMemorySize, AT_SMEM);
    attn_kernel<<<dim3(4, G_, B_ * H_), 128, AT_SMEM>>>(y);
}